// round 2
// baseline (speedup 1.0000x reference)
#include <cuda_runtime.h>
#include <cuda_bf16.h>
#include <math_constants.h>
#include <cstdint>
#include <cstddef>

#define DEMB 768
#define KSEL 32
#define K2   64                       // per-strip / refine candidate count
#define KC   32                       // k-chunk
#define NCHUNK (DEMB / KC)            // 24
#define TILE_N 64
#define TILES_PER_STRIP 11
#define STRIP (TILE_N * TILES_PER_STRIP)   // 704
#define MAXB 256
#define MAXSTRIP 320

// ---- device scratch (no allocations allowed) ----
__device__ __align__(16) __nv_bfloat16 g_Qb[MAXB * DEMB];            // Q in bf16
__device__ float g_candv[(size_t)MAXB * MAXSTRIP * K2];              // approx dists
__device__ int   g_candi[(size_t)MAXB * MAXSTRIP * K2];              // indices

// ---------------- Q fp32 -> bf16 ----------------
__global__ void convq_kernel(const float* __restrict__ Q, int total) {
    int i = blockIdx.x * blockDim.x + threadIdx.x;
    if (i < total) g_Qb[i] = __float2bfloat16(Q[i]);
}

__device__ __forceinline__ void mma16816(float* c, const uint32_t* a, const uint32_t* b) {
    asm volatile(
        "mma.sync.aligned.m16n8k16.row.col.f32.bf16.bf16.f32 "
        "{%0,%1,%2,%3}, {%4,%5,%6,%7}, {%8,%9}, {%0,%1,%2,%3};"
        : "+f"(c[0]), "+f"(c[1]), "+f"(c[2]), "+f"(c[3])
        : "r"(a[0]), "r"(a[1]), "r"(a[2]), "r"(a[3]), "r"(b[0]), "r"(b[1]));
}

// ---------------- fused bf16-MMA distance GEMM + per-strip top-64 ----------------
// grid.x = nstrip; 256 threads = 8 warps; M=256 (all queries), N-tile=64, KC=32.
// Warp layout: wm = warp&3 (M, 64 rows each), wn = warp>>2 (N, 32 cols each).
__global__ __launch_bounds__(256, 2)
void gemm_topk_kernel(const float* __restrict__ X, int B, int N)
{
    // union: pipeline buffers (25.6KB) vs half-tile dist matrix (33.8KB)
    __shared__ __align__(16) char sm_raw[256 * 33 * 4];
    __nv_bfloat16* Qs = (__nv_bfloat16*)sm_raw;               // [256][40] halves
    __nv_bfloat16* Xs = (__nv_bfloat16*)(sm_raw + 20480);     // [64][40] halves
    float* dist = (float*)sm_raw;                             // [256][33]
    __shared__ float sm_x2[TILE_N];

    const int tid  = threadIdx.x;
    const int lane = tid & 31;
    const int warp = tid >> 5;
    const int wm = warp & 3, wn = warp >> 2;
    const int fr = lane >> 2, fc = lane & 3;
    const int strip0 = blockIdx.x * STRIP;

    // per-thread (query = tid) running top-K2 over this strip (local memory)
    float vals[K2]; int ids[K2];
    #pragma unroll 1
    for (int i = 0; i < K2; i++) { vals[i] = CUDART_INF_F; ids[i] = 0x7fffffff; }
    float thresh = CUDART_INF_F;

    uint4  qreg[4];
    float4 xreg[2];

    for (int t = 0; t < TILES_PER_STRIP; t++) {
        const int n0 = strip0 + t * TILE_N;
        if (tid < TILE_N) sm_x2[tid] = 0.f;
        __syncthreads();   // also fences previous tile's dist reads vs new stores

        // prefetch chunk 0
        {
            #pragma unroll
            for (int p = 0; p < 4; p++) {
                int row = p * 64 + (tid >> 2);
                qreg[p] = *(const uint4*)&g_Qb[row * DEMB + (tid & 3) * 8];
            }
            #pragma unroll
            for (int p = 0; p < 2; p++) {
                int row = p * 32 + (tid >> 3);
                int ng  = n0 + row;
                xreg[p] = (ng < N) ? *(const float4*)&X[(size_t)ng * DEMB + (tid & 7) * 4]
                                   : make_float4(0.f, 0.f, 0.f, 0.f);
            }
        }

        float acc[4][4][4];
        #pragma unroll
        for (int mi = 0; mi < 4; mi++)
            #pragma unroll
            for (int ni = 0; ni < 4; ni++)
                #pragma unroll
                for (int r = 0; r < 4; r++) acc[mi][ni][r] = 0.f;

        for (int ch = 0; ch < NCHUNK; ch++) {
            // ---- store staged regs to smem (+ x2 accumulation) ----
            #pragma unroll
            for (int p = 0; p < 4; p++) {
                int row = p * 64 + (tid >> 2);
                *(uint4*)&Qs[row * 40 + (tid & 3) * 8] = qreg[p];
            }
            #pragma unroll
            for (int p = 0; p < 2; p++) {
                int row = p * 32 + (tid >> 3);
                float4 v = xreg[p];
                __nv_bfloat162 h0 = __floats2bfloat162_rn(v.x, v.y);
                __nv_bfloat162 h1 = __floats2bfloat162_rn(v.z, v.w);
                uint2 pk;
                pk.x = *(uint32_t*)&h0; pk.y = *(uint32_t*)&h1;
                *(uint2*)&Xs[row * 40 + (tid & 7) * 4] = pk;
                float sq = fmaf(v.x, v.x, fmaf(v.y, v.y, fmaf(v.z, v.z, v.w * v.w)));
                sq += __shfl_down_sync(0xffffffffu, sq, 4, 8);
                sq += __shfl_down_sync(0xffffffffu, sq, 2, 8);
                sq += __shfl_down_sync(0xffffffffu, sq, 1, 8);
                if ((tid & 7) == 0) sm_x2[row] += sq;
            }
            __syncthreads();

            // ---- prefetch next chunk ----
            if (ch + 1 < NCHUNK) {
                const int k0 = (ch + 1) * KC;
                #pragma unroll
                for (int p = 0; p < 4; p++) {
                    int row = p * 64 + (tid >> 2);
                    qreg[p] = *(const uint4*)&g_Qb[row * DEMB + k0 + (tid & 3) * 8];
                }
                #pragma unroll
                for (int p = 0; p < 2; p++) {
                    int row = p * 32 + (tid >> 3);
                    int ng  = n0 + row;
                    xreg[p] = (ng < N) ? *(const float4*)&X[(size_t)ng * DEMB + k0 + (tid & 7) * 4]
                                       : make_float4(0.f, 0.f, 0.f, 0.f);
                }
            }

            // ---- tensor-core MMAs on the chunk ----
            const uint32_t* Qu = (const uint32_t*)Qs;
            const uint32_t* Xu = (const uint32_t*)Xs;
            #pragma unroll
            for (int ks = 0; ks < 2; ks++) {
                const int kb = ks * 8;   // u32 offset within 40-half row
                uint32_t a[4][4], bfrag[4][2];
                #pragma unroll
                for (int mi = 0; mi < 4; mi++) {
                    int r0 = wm * 64 + mi * 16 + fr;
                    a[mi][0] = Qu[r0 * 20 + kb + fc];
                    a[mi][1] = Qu[(r0 + 8) * 20 + kb + fc];
                    a[mi][2] = Qu[r0 * 20 + kb + 4 + fc];
                    a[mi][3] = Qu[(r0 + 8) * 20 + kb + 4 + fc];
                }
                #pragma unroll
                for (int ni = 0; ni < 4; ni++) {
                    int nn = wn * 32 + ni * 8 + fr;
                    bfrag[ni][0] = Xu[nn * 20 + kb + fc];
                    bfrag[ni][1] = Xu[nn * 20 + kb + 4 + fc];
                }
                #pragma unroll
                for (int mi = 0; mi < 4; mi++)
                    #pragma unroll
                    for (int ni = 0; ni < 4; ni++)
                        mma16816(acc[mi][ni], a[mi], bfrag[ni]);
            }
            __syncthreads();
        }

        // ---- epilogue: two 32-col halves -> smem dist -> per-query scan ----
        #pragma unroll
        for (int h = 0; h < 2; h++) {
            if (wn == h) {
                #pragma unroll
                for (int mi = 0; mi < 4; mi++)
                    #pragma unroll
                    for (int ni = 0; ni < 4; ni++) {
                        int r0 = wm * 64 + mi * 16 + fr;
                        int cc = ni * 8 + 2 * fc;
                        int ng = n0 + h * 32 + cc;
                        float x2a = sm_x2[h * 32 + cc];
                        float x2b = sm_x2[h * 32 + cc + 1];
                        float v0 = (ng     < N) ? fmaf(-2.f, acc[mi][ni][0], x2a) : CUDART_INF_F;
                        float v1 = (ng + 1 < N) ? fmaf(-2.f, acc[mi][ni][1], x2b) : CUDART_INF_F;
                        float v2 = (ng     < N) ? fmaf(-2.f, acc[mi][ni][2], x2a) : CUDART_INF_F;
                        float v3 = (ng + 1 < N) ? fmaf(-2.f, acc[mi][ni][3], x2b) : CUDART_INF_F;
                        dist[r0 * 33 + cc]           = v0;
                        dist[r0 * 33 + cc + 1]       = v1;
                        dist[(r0 + 8) * 33 + cc]     = v2;
                        dist[(r0 + 8) * 33 + cc + 1] = v3;
                    }
            }
            __syncthreads();
            const float* drow = &dist[tid * 33];
            const int nbase = n0 + h * 32;
            #pragma unroll 4
            for (int j = 0; j < 32; j++) {
                float v = drow[j];
                if (v < thresh) {
                    int pos = K2 - 1;
                    while (pos > 0 && vals[pos - 1] > v) {
                        vals[pos] = vals[pos - 1]; ids[pos] = ids[pos - 1]; pos--;
                    }
                    vals[pos] = v; ids[pos] = nbase + j;
                    thresh = vals[K2 - 1];
                }
            }
            __syncthreads();
        }
    }

    // write per-strip candidates: layout [query][strip][slot]
    size_t base = ((size_t)tid * gridDim.x + blockIdx.x) * K2;
    #pragma unroll 1
    for (int s = 0; s < K2; s++) {
        g_candv[base + s] = vals[s];
        g_candi[base + s] = ids[s];
    }
}

// ---------------- merge + exact fp32 refine + epilogue ----------------
__global__ __launch_bounds__(256)
void merge_refine_kernel(const float* __restrict__ Q, const int* __restrict__ qsys,
                         const float* __restrict__ X, const float* __restrict__ Y,
                         const int* __restrict__ sys, const float* __restrict__ W,
                         const float* __restrict__ bias, float* __restrict__ out,
                         int B, int N, int nstrip)
{
    __shared__ float qs[DEMB];
    __shared__ float red[256];
    __shared__ unsigned long long skey[256];
    __shared__ float cv[K2];
    __shared__ int   ci[K2];
    __shared__ float selv[KSEL];
    __shared__ int   seli[KSEL];

    const int b = blockIdx.x, tid = threadIdx.x;
    const int warp = tid >> 5, lane = tid & 31;

    // load query row + q2
    float q2p = 0.f;
    for (int k = tid; k < DEMB; k += 256) {
        float v = Q[(size_t)b * DEMB + k];
        qs[k] = v; q2p = fmaf(v, v, q2p);
    }
    red[tid] = q2p; __syncthreads();
    for (int s = 128; s > 0; s >>= 1) { if (tid < s) red[tid] += red[tid + s]; __syncthreads(); }
    const float q2 = red[0];
    __syncthreads();

    // per-thread top-K2 over the candidate pool
    float vals[K2]; int ids[K2];
    #pragma unroll 1
    for (int i = 0; i < K2; i++) { vals[i] = CUDART_INF_F; ids[i] = 0x7fffffff; }
    float thresh = CUDART_INF_F;
    const size_t cbase = (size_t)b * nstrip * K2;
    const int total = nstrip * K2;
    for (int e = tid; e < total; e += 256) {
        float v = g_candv[cbase + e];
        if (v < thresh) {
            int idx = g_candi[cbase + e];
            int pos = K2 - 1;
            while (pos > 0 && vals[pos - 1] > v) {
                vals[pos] = vals[pos - 1]; ids[pos] = ids[pos - 1]; pos--;
            }
            vals[pos] = v; ids[pos] = idx;
            thresh = vals[K2 - 1];
        }
    }

    // tournament: global approx top-K2 (keys = (mapped val, idx), unique)
    int head = 0;
    for (int r = 0; r < K2; r++) {
        unsigned long long key;
        if (head < K2 && vals[head] < CUDART_INF_F) {
            unsigned u = __float_as_uint(vals[head]);
            u = (u & 0x80000000u) ? ~u : (u | 0x80000000u);
            key = ((unsigned long long)u << 32) | (unsigned)ids[head];
        } else key = ~0ULL;
        skey[tid] = key; __syncthreads();
        for (int s = 128; s > 0; s >>= 1) {
            if (tid < s && skey[tid + s] < skey[tid]) skey[tid] = skey[tid + s];
            __syncthreads();
        }
        unsigned long long wk = skey[0];
        __syncthreads();
        if (key == wk && key != ~0ULL) head++;
        if (tid == 0) ci[r] = (int)(wk & 0xffffffffu);
        __syncthreads();
    }

    // exact fp32 refine of K2 candidates: d2 = q2 + x2 - 2*dot
    for (int c = warp; c < K2; c += 8) {
        const float* xr = &X[(size_t)ci[c] * DEMB];
        float dot = 0.f, xx = 0.f;
        for (int k = lane; k < DEMB; k += 32) {
            float xv = xr[k];
            dot = fmaf(qs[k], xv, dot);
            xx  = fmaf(xv, xv, xx);
        }
        #pragma unroll
        for (int off = 16; off > 0; off >>= 1) {
            dot += __shfl_xor_sync(0xffffffffu, dot, off);
            xx  += __shfl_xor_sync(0xffffffffu, xx,  off);
        }
        if (lane == 0) cv[c] = fmaf(-2.f, dot, q2 + xx);
    }
    __syncthreads();

    // rank the 64 refined candidates, take top-32 in (d2, idx) order
    if (tid < K2) {
        unsigned u = __float_as_uint(cv[tid]);
        u = (u & 0x80000000u) ? ~u : (u | 0x80000000u);
        skey[tid] = ((unsigned long long)u << 32) | (unsigned)ci[tid];
    }
    __syncthreads();
    if (tid < K2) {
        unsigned long long me = skey[tid];
        int rank = 0;
        #pragma unroll
        for (int j = 0; j < K2; j++) rank += (skey[j] < me);
        if (rank < KSEL) { selv[rank] = cv[tid]; seli[rank] = ci[tid]; }
    }
    __syncthreads();

    // local layer + prefix softmax (warp 0, lane = rank)
    if (tid < KSEL) {
        float d2v = selv[tid];
        int   idx = seli[tid];
        float sc  = Y[idx];
        int   ls  = sys[idx];
        int   qsv = qsys[b];
        float nd  = (ls == qsv) ? fmaf(d2v, W[1], bias[1]) : fmaf(d2v, W[0], bias[0]);
        float neg = -nd;
        float mmax = neg;
        #pragma unroll
        for (int off = 16; off > 0; off >>= 1)
            mmax = fmaxf(mmax, __shfl_xor_sync(0xffffffffu, mmax, off));
        float w  = expf(neg - mmax);
        float ws = w * sc;
        float cw = w, cws = ws;
        #pragma unroll
        for (int off = 1; off < KSEL; off <<= 1) {
            float tw  = __shfl_up_sync(0xffffffffu, cw,  off);
            float tws = __shfl_up_sync(0xffffffffu, cws, off);
            if (tid >= off) { cw += tw; cws += tws; }
        }
        out[(size_t)b * KSEL + tid] = nd;
        out[(size_t)B * KSEL + (size_t)b * KSEL + tid] = cws / cw;
    }
}

extern "C" void kernel_launch(void* const* d_in, const int* in_sizes, int n_in,
                              void* d_out, int out_size)
{
    const float* Q    = (const float*)d_in[0];
    const int*   qsys = (const int*)  d_in[1];
    const float* X    = (const float*)d_in[2];
    const float* Y    = (const float*)d_in[3];
    const int*   sys  = (const int*)  d_in[4];
    const float* W    = (const float*)d_in[5];
    const float* bias = (const float*)d_in[6];
    float* out = (float*)d_out;

    int B = in_sizes[1];
    int N = in_sizes[3];
    int nstrip = (N + STRIP - 1) / STRIP;

    convq_kernel<<<(B * DEMB + 255) / 256, 256>>>(Q, B * DEMB);
    gemm_topk_kernel<<<nstrip, 256>>>(X, B, N);
    merge_refine_kernel<<<B, 256>>>(Q, qsys, X, Y, sys, W, bias, out, B, N, nstrip);
}

// round 3
// speedup vs baseline: 23.9574x; 23.9574x over previous
#include <cuda_runtime.h>
#include <cuda_bf16.h>
#include <math_constants.h>
#include <cstdint>
#include <cstddef>

#define DEMB 768
#define KSEL 32
#define K2   64
#define KC   16
#define NK   (DEMB / KC)      // 48
#define MAXB 256
#define MAXN 200256           // padded
#define BUFCAP 4096

// ---- device scratch (no allocations allowed) ----
__device__ __align__(16) __nv_bfloat16 g_Qb[MAXB * DEMB];
__device__ __align__(16) float g_x2[MAXN];
__device__ __align__(16) float g_S[(size_t)MAXB * (size_t)MAXN];

// ---------------- Q fp32 -> bf16 ----------------
__global__ void convq_kernel(const float* __restrict__ Q, int total) {
    int i = blockIdx.x * blockDim.x + threadIdx.x;
    if (i < total) g_Qb[i] = __float2bfloat16(Q[i]);
}

// ---------------- row squared norms of X ----------------
__global__ void x2_kernel(const float* __restrict__ X, int N, int K) {
    int w = (int)((blockIdx.x * blockDim.x + threadIdx.x) >> 5);
    int lane = threadIdx.x & 31;
    if (w >= N) return;
    const float* row = X + (size_t)w * K;
    float s = 0.f;
    for (int k = lane; k < K; k += 32) { float v = row[k]; s = fmaf(v, v, s); }
    #pragma unroll
    for (int off = 16; off > 0; off >>= 1) s += __shfl_xor_sync(0xffffffffu, s, off);
    if (lane == 0) g_x2[w] = s;
}

__device__ __forceinline__ void mma16816(float* c, const uint32_t* a, const uint32_t* b) {
    asm volatile(
        "mma.sync.aligned.m16n8k16.row.col.f32.bf16.bf16.f32 "
        "{%0,%1,%2,%3}, {%4,%5,%6,%7}, {%8,%9}, {%0,%1,%2,%3};"
        : "+f"(c[0]), "+f"(c[1]), "+f"(c[2]), "+f"(c[3])
        : "r"(a[0]), "r"(a[1]), "r"(a[2]), "r"(a[3]), "r"(b[0]), "r"(b[1]));
}

// ---------------- bf16 MMA GEMM: g_S = x2 - 2 * Q @ X^T ----------------
// CTA 128x128, 256 thr, 8 warps (wm in {0,1} x 64 rows, wn in {0..3} x 32 cols)
#define APITCH 24   // halves per smem row (12 u32)
__global__ __launch_bounds__(256, 2)
void gemm_bf16_kernel(const float* __restrict__ X, int B, int N)
{
    __shared__ __align__(16) __nv_bfloat16 Asm[2][128 * APITCH];
    __shared__ __align__(16) __nv_bfloat16 Bsm[2][128 * APITCH];

    const int tid  = threadIdx.x;
    const int lane = tid & 31;
    const int warp = tid >> 5;
    const int wm = warp >> 2, wn = warp & 3;
    const int fr = lane >> 2, fc = lane & 3;
    const int m0 = blockIdx.y * 128;
    const int n0 = blockIdx.x * 128;

    const int lr = tid >> 1;       // 0..127
    const int lh = tid & 1;        // k-half (8 halves each)

    float acc[4][4][4];
    #pragma unroll
    for (int mi = 0; mi < 4; mi++)
        #pragma unroll
        for (int ni = 0; ni < 4; ni++)
            #pragma unroll
            for (int r = 0; r < 4; r++) acc[mi][ni][r] = 0.f;

    const bool a_ok = (m0 + lr) < B;
    const bool b_ok = (n0 + lr) < N;
    const __nv_bfloat16* agp = &g_Qb[(size_t)(m0 + lr) * DEMB + lh * 8];
    const float*         bgp = &X[(size_t)(b_ok ? (n0 + lr) : 0) * DEMB + lh * 8];

    uint4  aq = make_uint4(0, 0, 0, 0);
    float4 x0 = make_float4(0.f, 0.f, 0.f, 0.f), x1 = x0;

    // prologue: stage 0
    if (a_ok) aq = *(const uint4*)agp;
    if (b_ok) { x0 = *(const float4*)bgp; x1 = *(const float4*)(bgp + 4); }
    {
        *(uint4*)&Asm[0][lr * APITCH + lh * 8] = aq;
        __nv_bfloat162 h0 = __floats2bfloat162_rn(x0.x, x0.y);
        __nv_bfloat162 h1 = __floats2bfloat162_rn(x0.z, x0.w);
        __nv_bfloat162 h2 = __floats2bfloat162_rn(x1.x, x1.y);
        __nv_bfloat162 h3 = __floats2bfloat162_rn(x1.z, x1.w);
        uint4 bq = make_uint4(*(uint32_t*)&h0, *(uint32_t*)&h1, *(uint32_t*)&h2, *(uint32_t*)&h3);
        *(uint4*)&Bsm[0][lr * APITCH + lh * 8] = bq;
    }
    __syncthreads();

    for (int ks = 0; ks < NK; ks++) {
        const int cur = ks & 1;
        // issue next-stage global loads early
        if (ks + 1 < NK) {
            const int koff = (ks + 1) * KC;
            if (a_ok) aq = *(const uint4*)(agp + koff);
            if (b_ok) { x0 = *(const float4*)(bgp + koff); x1 = *(const float4*)(bgp + koff + 4); }
        }

        // compute on current buffer
        const uint32_t* Au = (const uint32_t*)&Asm[cur][0];
        const uint32_t* Bu = (const uint32_t*)&Bsm[cur][0];
        uint32_t bf[4][2];
        #pragma unroll
        for (int ni = 0; ni < 4; ni++) {
            int nn = wn * 32 + ni * 8 + fr;
            bf[ni][0] = Bu[nn * 12 + fc];
            bf[ni][1] = Bu[nn * 12 + 4 + fc];
        }
        #pragma unroll
        for (int mi = 0; mi < 4; mi++) {
            int rr = wm * 64 + mi * 16 + fr;
            uint32_t a[4];
            a[0] = Au[rr * 12 + fc];
            a[1] = Au[(rr + 8) * 12 + fc];
            a[2] = Au[rr * 12 + 4 + fc];
            a[3] = Au[(rr + 8) * 12 + 4 + fc];
            #pragma unroll
            for (int ni = 0; ni < 4; ni++)
                mma16816(acc[mi][ni], a, bf[ni]);
        }

        // store next stage
        if (ks + 1 < NK) {
            const int nxt = cur ^ 1;
            *(uint4*)&Asm[nxt][lr * APITCH + lh * 8] = aq;
            __nv_bfloat162 h0 = __floats2bfloat162_rn(x0.x, x0.y);
            __nv_bfloat162 h1 = __floats2bfloat162_rn(x0.z, x0.w);
            __nv_bfloat162 h2 = __floats2bfloat162_rn(x1.x, x1.y);
            __nv_bfloat162 h3 = __floats2bfloat162_rn(x1.z, x1.w);
            uint4 bq = make_uint4(*(uint32_t*)&h0, *(uint32_t*)&h1, *(uint32_t*)&h2, *(uint32_t*)&h3);
            *(uint4*)&Bsm[nxt][lr * APITCH + lh * 8] = bq;
        }
        __syncthreads();
    }

    // epilogue: d2 = x2[n] - 2*dot, direct float2 stores
    #pragma unroll
    for (int ni = 0; ni < 4; ni++) {
        int c = n0 + wn * 32 + ni * 8 + 2 * fc;
        if (c + 1 >= N && c >= N) continue;
        float x2a = g_x2[c];
        float x2b = (c + 1 < N) ? g_x2[c + 1] : 0.f;
        #pragma unroll
        for (int mi = 0; mi < 4; mi++) {
            int r = m0 + wm * 64 + mi * 16 + fr;
            if (r < B) {
                if (c + 1 < N) {
                    float2 v0 = make_float2(fmaf(-2.f, acc[mi][ni][0], x2a),
                                            fmaf(-2.f, acc[mi][ni][1], x2b));
                    *(float2*)&g_S[(size_t)r * N + c] = v0;
                } else {
                    g_S[(size_t)r * N + c] = fmaf(-2.f, acc[mi][ni][0], x2a);
                }
            }
            if (r + 8 < B) {
                if (c + 1 < N) {
                    float2 v1 = make_float2(fmaf(-2.f, acc[mi][ni][2], x2a),
                                            fmaf(-2.f, acc[mi][ni][3], x2b));
                    *(float2*)&g_S[(size_t)(r + 8) * N + c] = v1;
                } else {
                    g_S[(size_t)(r + 8) * N + c] = fmaf(-2.f, acc[mi][ni][2], x2a);
                }
            }
        }
    }
}

// ---------------- per-query: threshold filter -> top-64 -> exact refine -> epilogue ----------------
__device__ __forceinline__ unsigned long long mkkey(float v, int idx) {
    unsigned u = __float_as_uint(v);
    u = (u & 0x80000000u) ? ~u : (u | 0x80000000u);
    return ((unsigned long long)u << 32) | (unsigned)idx;
}
__device__ __forceinline__ float keyval(unsigned long long k) {
    unsigned u = (unsigned)(k >> 32);
    u = (u & 0x80000000u) ? (u & 0x7fffffffu) : ~u;
    return __uint_as_float(u);
}

__global__ __launch_bounds__(256)
void select_kernel(const float* __restrict__ Q, const int* __restrict__ qsys,
                   const float* __restrict__ X, const float* __restrict__ Y,
                   const int* __restrict__ sys, const float* __restrict__ W,
                   const float* __restrict__ bias, float* __restrict__ out,
                   int B, int N)
{
    __shared__ float qs[DEMB];
    __shared__ float red[256];
    __shared__ unsigned long long buf[BUFCAP];
    __shared__ int sh_cnt;
    __shared__ float cv[K2];
    __shared__ int   ci[K2];
    __shared__ unsigned long long rkey[K2];
    __shared__ float selv[KSEL];
    __shared__ int   seli[KSEL];

    const int b = blockIdx.x, tid = threadIdx.x;
    const int warp = tid >> 5, lane = tid & 31;

    // query row + q2
    float q2p = 0.f;
    for (int k = tid; k < DEMB; k += 256) {
        float v = Q[(size_t)b * DEMB + k];
        qs[k] = v; q2p = fmaf(v, v, q2p);
    }
    red[tid] = q2p; __syncthreads();
    for (int s = 128; s > 0; s >>= 1) { if (tid < s) red[tid] += red[tid + s]; __syncthreads(); }
    const float q2 = red[0];
    __syncthreads();

    const float* srow = &g_S[(size_t)b * N];
    const int n4lim = N & ~3;

    // pass 1: per-thread min
    float mn = CUDART_INF_F;
    for (int n = tid * 4; n < n4lim; n += 1024) {
        float4 v = *(const float4*)&srow[n];
        mn = fminf(mn, fminf(fminf(v.x, v.y), fminf(v.z, v.w)));
    }
    for (int n = n4lim + tid; n < N; n += 256) mn = fminf(mn, srow[n]);
    red[tid] = mn;
    __syncthreads();
    // bitonic sort 256 floats ascending
    for (int k = 2; k <= 256; k <<= 1) {
        for (int j = k >> 1; j > 0; j >>= 1) {
            int ixj = tid ^ j;
            if (ixj > tid) {
                float a = red[tid], c = red[ixj];
                bool up = ((tid & k) == 0);
                if ((a > c) == up) { red[tid] = c; red[ixj] = a; }
            }
            __syncthreads();
        }
    }
    const float t0 = red[K2 - 1];   // 64th smallest per-thread min
    __syncthreads();

    // init buffer
    for (int i = tid; i < BUFCAP; i += 256) buf[i] = ~0ULL;
    if (tid == 0) sh_cnt = 0;
    __syncthreads();

    // pass 2: filter v <= t0
    for (int n = tid * 4; n < n4lim; n += 1024) {
        float4 v = *(const float4*)&srow[n];
        if (v.x <= t0) { int p = atomicAdd(&sh_cnt, 1); if (p < BUFCAP) buf[p] = mkkey(v.x, n); }
        if (v.y <= t0) { int p = atomicAdd(&sh_cnt, 1); if (p < BUFCAP) buf[p] = mkkey(v.y, n + 1); }
        if (v.z <= t0) { int p = atomicAdd(&sh_cnt, 1); if (p < BUFCAP) buf[p] = mkkey(v.z, n + 2); }
        if (v.w <= t0) { int p = atomicAdd(&sh_cnt, 1); if (p < BUFCAP) buf[p] = mkkey(v.w, n + 3); }
    }
    for (int n = n4lim + tid; n < N; n += 256) {
        float v = srow[n];
        if (v <= t0) { int p = atomicAdd(&sh_cnt, 1); if (p < BUFCAP) buf[p] = mkkey(v, n); }
    }
    __syncthreads();
    int cnt = sh_cnt; if (cnt > BUFCAP) cnt = BUFCAP;

    // bitonic sort buf[0..P) ascending (padded with max keys)
    int P = K2; while (P < cnt) P <<= 1;
    for (int k = 2; k <= P; k <<= 1) {
        for (int j = k >> 1; j > 0; j >>= 1) {
            for (int i = tid; i < P; i += 256) {
                int ixj = i ^ j;
                if (ixj > i) {
                    unsigned long long a = buf[i], c = buf[ixj];
                    bool up = ((i & k) == 0);
                    if ((a > c) == up) { buf[i] = c; buf[ixj] = a; }
                }
            }
            __syncthreads();
        }
    }

    // approx top-64 candidates
    if (tid < K2) ci[tid] = (int)(buf[tid] & 0xffffffffu);
    __syncthreads();

    // exact fp32 refine
    for (int c = warp; c < K2; c += 8) {
        const float* xr = &X[(size_t)ci[c] * DEMB];
        float dot = 0.f, xx = 0.f;
        for (int k = lane; k < DEMB; k += 32) {
            float xv = xr[k];
            dot = fmaf(qs[k], xv, dot);
            xx  = fmaf(xv, xv, xx);
        }
        #pragma unroll
        for (int off = 16; off > 0; off >>= 1) {
            dot += __shfl_xor_sync(0xffffffffu, dot, off);
            xx  += __shfl_xor_sync(0xffffffffu, xx,  off);
        }
        if (lane == 0) cv[c] = fmaf(-2.f, dot, q2 + xx);
    }
    __syncthreads();

    // rank 64 refined candidates -> top-32 by (d2, idx)
    if (tid < K2) rkey[tid] = mkkey(cv[tid], ci[tid]);
    __syncthreads();
    if (tid < K2) {
        unsigned long long me = rkey[tid];
        int rank = 0;
        #pragma unroll
        for (int j = 0; j < K2; j++) rank += (rkey[j] < me);
        if (rank < KSEL) { selv[rank] = cv[tid]; seli[rank] = ci[tid]; }
    }
    __syncthreads();

    // local layer + prefix softmax
    if (tid < KSEL) {
        float d2v = selv[tid];
        int   idx = seli[tid];
        float sc  = Y[idx];
        int   ls  = sys[idx];
        int   qsv = qsys[b];
        float nd  = (ls == qsv) ? fmaf(d2v, W[1], bias[1]) : fmaf(d2v, W[0], bias[0]);
        float neg = -nd;
        float mmax = neg;
        #pragma unroll
        for (int off = 16; off > 0; off >>= 1)
            mmax = fmaxf(mmax, __shfl_xor_sync(0xffffffffu, mmax, off));
        float w  = expf(neg - mmax);
        float ws = w * sc;
        float cw = w, cws = ws;
        #pragma unroll
        for (int off = 1; off < KSEL; off <<= 1) {
            float tw  = __shfl_up_sync(0xffffffffu, cw,  off);
            float tws = __shfl_up_sync(0xffffffffu, cws, off);
            if (tid >= off) { cw += tw; cws += tws; }
        }
        out[(size_t)b * KSEL + tid] = nd;
        out[(size_t)B * KSEL + (size_t)b * KSEL + tid] = cws / cw;
    }
}

extern "C" void kernel_launch(void* const* d_in, const int* in_sizes, int n_in,
                              void* d_out, int out_size)
{
    const float* Q    = (const float*)d_in[0];
    const int*   qsys = (const int*)  d_in[1];
    const float* X    = (const float*)d_in[2];
    const float* Y    = (const float*)d_in[3];
    const int*   sys  = (const int*)  d_in[4];
    const float* W    = (const float*)d_in[5];
    const float* bias = (const float*)d_in[6];
    float* out = (float*)d_out;

    int B = in_sizes[1];
    int N = in_sizes[3];

    convq_kernel<<<(B * DEMB + 255) / 256, 256>>>(Q, B * DEMB);
    x2_kernel<<<(N + 7) / 8, 256>>>(X, N, DEMB);
    dim3 grid((N + 127) / 128, (B + 127) / 128);
    gemm_bf16_kernel<<<grid, 256>>>(X, B, N);
    select_kernel<<<B, 256>>>(Q, qsys, X, Y, sys, W, bias, out, B, N);
}

// round 5
// speedup vs baseline: 28.8991x; 1.2063x over previous
#include <cuda_runtime.h>
#include <cuda_bf16.h>
#include <math_constants.h>
#include <cstdint>
#include <cstddef>

#define DEMB 768
#define KSEL 32
#define K2   64
#define TILE_N 128
#define KC   16
#define NCH  (DEMB / KC)        // 48
#define STAGES 4
#define MAXB 256
#define MAXN 200000
#define MAXT ((MAXN + TILE_N - 1) / TILE_N)   // 1563
#define BUFCAP 4096
#define BMPAD 2048

// stage layout: A (256 rows x 48B) then B (128 rows x 80B fp32)
#define A_BYTES (256 * 48)
#define B_BYTES (128 * 80)
#define STAGE_BYTES (A_BYTES + B_BYTES)       // 22528

// ---- device scratch ----
__device__ __align__(16) __nv_bfloat16 g_Qb[MAXB * DEMB];
__device__ __align__(16) float g_S[(size_t)MAXB * (size_t)MAXN];
__device__ __align__(16) float g_blkmin[MAXB * MAXT];

__device__ __forceinline__ uint32_t smem_u32(const void* p) {
    uint32_t a;
    asm("{ .reg .u64 t; cvta.to.shared.u64 t, %1; cvt.u32.u64 %0, t; }" : "=r"(a) : "l"(p));
    return a;
}
__device__ __forceinline__ void cp16(uint32_t dst, const void* src) {
    asm volatile("cp.async.ca.shared.global [%0], [%1], 16;" :: "r"(dst), "l"(src));
}
#define CP_COMMIT() asm volatile("cp.async.commit_group;" ::: "memory")
#define CP_WAIT2()  asm volatile("cp.async.wait_group 2;" ::: "memory")
#define LDSM4(r0, r1, r2, r3, a) \
    asm volatile("ldmatrix.sync.aligned.m8n8.x4.shared.b16 {%0,%1,%2,%3}, [%4];" \
        : "=r"(r0), "=r"(r1), "=r"(r2), "=r"(r3) : "r"(a))

__device__ __forceinline__ void mma16816(float* c, const uint32_t* a, const uint32_t* b) {
    asm volatile(
        "mma.sync.aligned.m16n8k16.row.col.f32.bf16.bf16.f32 "
        "{%0,%1,%2,%3}, {%4,%5,%6,%7}, {%8,%9}, {%0,%1,%2,%3};"
        : "+f"(c[0]), "+f"(c[1]), "+f"(c[2]), "+f"(c[3])
        : "r"(a[0]), "r"(a[1]), "r"(a[2]), "r"(a[3]), "r"(b[0]), "r"(b[1]));
}
__device__ __forceinline__ unsigned enc(float f) {
    unsigned u = __float_as_uint(f);
    return (u & 0x80000000u) ? ~u : (u | 0x80000000u);
}
__device__ __forceinline__ float dec(unsigned u) {
    u = (u & 0x80000000u) ? (u & 0x7fffffffu) : ~u;
    return __uint_as_float(u);
}
__device__ __forceinline__ unsigned long long mkkey(float v, int idx) {
    return ((unsigned long long)enc(v) << 32) | (unsigned)idx;
}

// ---------------- Q fp32 -> bf16 (zero-pad to MAXB rows) ----------------
__global__ void convq_kernel(const float* __restrict__ Q, int total) {
    int i = blockIdx.x * blockDim.x + threadIdx.x;
    if (i < MAXB * DEMB)
        g_Qb[i] = __float2bfloat16(i < total ? Q[i] : 0.f);
}

// ---------------- HMMA GEMM, M=256 x N-tile=128, cp.async 4-stage ----------------
__global__ __launch_bounds__(512, 1)
void gemm_hmma_kernel(const float* __restrict__ X, int B, int N, int ntiles)
{
    extern __shared__ __align__(16) char dsm[];
    __shared__ float    x2p[TILE_N];
    __shared__ unsigned bmu[256];

    const int tid  = threadIdx.x;
    const int lane = tid & 31;
    const int warp = tid >> 5;
    const int wm = warp >> 2, wn = warp & 3;
    const int fr = lane >> 2, fc = lane & 3;
    const int n0 = blockIdx.x * TILE_N;

    const uint32_t sb = smem_u32(dsm);

    // cp.async source/dest assignments
    const int rA = tid >> 1, hA = tid & 1;          // A: 256 rows x 2 chunks of 16B
    const int rB = tid >> 2, cB = tid & 3;          // B: 128 rows x 4 chunks of 16B
    const int rBc = min(n0 + rB, N - 1);
    const __nv_bfloat16* asrc = &g_Qb[(size_t)rA * DEMB + hA * 8];
    const float*         bsrc = &X[(size_t)rBc * DEMB + cB * 4];
    const uint32_t adst = sb + rA * 48 + hA * 16;
    const uint32_t bdst = sb + A_BYTES + rB * 80 + cB * 16;

    if (tid < 256) bmu[tid] = 0xFFFFFFFFu;

    // prologue: stages 0..2
    #pragma unroll
    for (int s = 0; s < 3; s++) {
        const int kof = s * KC;
        cp16(adst + s * STAGE_BYTES, asrc + kof);
        cp16(bdst + s * STAGE_BYTES, bsrc + kof);
        CP_COMMIT();
    }

    float acc[4][4][4];
    #pragma unroll
    for (int mi = 0; mi < 4; mi++)
        #pragma unroll
        for (int ni = 0; ni < 4; ni++)
            #pragma unroll
            for (int r = 0; r < 4; r++) acc[mi][ni][r] = 0.f;

    float x2reg = 0.f;
    const uint32_t aoff_lane = ((lane & 7) + ((lane >> 3) & 1) * 8) * 48 + ((lane >> 4) & 1) * 16;

    for (int ch = 0; ch < NCH; ch++) {
        const int st = ch & 3;
        CP_WAIT2();
        __syncthreads();

        // prefetch stage ch+3
        if (ch + 3 < NCH) {
            const int kof = (ch + 3) * KC;
            const int sn = (ch + 3) & 3;
            cp16(adst + sn * STAGE_BYTES, asrc + kof);
            cp16(bdst + sn * STAGE_BYTES, bsrc + kof);
        }
        CP_COMMIT();   // commit unconditionally to keep group counts uniform

        const char* Ab = dsm + st * STAGE_BYTES;
        const char* Bb = Ab + A_BYTES;
        const uint32_t Abu = sb + st * STAGE_BYTES;

        // x2 accumulation: thread t<128 owns B row t (fp32 in smem)
        if (tid < TILE_N) {
            const float4* bp = (const float4*)(Bb + tid * 80);
            #pragma unroll
            for (int j = 0; j < 4; j++) {
                float4 v = bp[j];
                x2reg += fmaf(v.x, v.x, fmaf(v.y, v.y, fmaf(v.z, v.z, v.w * v.w)));
            }
        }

        // b fragments (fp32 -> bf16)
        uint32_t bf[4][2];
        #pragma unroll
        for (int ni = 0; ni < 4; ni++) {
            const char* brow = Bb + (wn * 32 + ni * 8 + fr) * 80 + fc * 8;
            float2 f0 = *(const float2*)brow;
            float2 f1 = *(const float2*)(brow + 32);
            __nv_bfloat162 h0 = __floats2bfloat162_rn(f0.x, f0.y);
            __nv_bfloat162 h1 = __floats2bfloat162_rn(f1.x, f1.y);
            bf[ni][0] = *(uint32_t*)&h0;
            bf[ni][1] = *(uint32_t*)&h1;
        }

        // a fragments via ldmatrix.x4 + MMAs
        #pragma unroll
        for (int mi = 0; mi < 4; mi++) {
            uint32_t a[4];
            LDSM4(a[0], a[1], a[2], a[3], Abu + (wm * 64 + mi * 16) * 48 + aoff_lane);
            #pragma unroll
            for (int ni = 0; ni < 4; ni++)
                mma16816(acc[mi][ni], a, bf[ni]);
        }
        __syncthreads();
    }

    if (tid < TILE_N) x2p[tid] = x2reg;
    __syncthreads();

    // ---- epilogue: dist = x2 - 2*dot, store + blockmin ----
    #pragma unroll
    for (int mi = 0; mi < 4; mi++) {
        const int R = wm * 64 + mi * 16 + fr;
        float mn0 = CUDART_INF_F, mn1 = CUDART_INF_F;
        #pragma unroll
        for (int ni = 0; ni < 4; ni++) {
            const int c = wn * 32 + ni * 8 + 2 * fc;
            const int n = n0 + c;
            const bool ok0 = n < N, ok1 = (n + 1) < N;
            float x2a = x2p[c], x2b = x2p[c + 1];
            float v0 = fmaf(-2.f, acc[mi][ni][0], x2a);
            float v1 = fmaf(-2.f, acc[mi][ni][1], x2b);
            float v2 = fmaf(-2.f, acc[mi][ni][2], x2a);
            float v3 = fmaf(-2.f, acc[mi][ni][3], x2b);
            if (R < B) {
                if (ok0 && ok1) *(float2*)&g_S[(size_t)R * N + n] = make_float2(v0, v1);
                else if (ok0) g_S[(size_t)R * N + n] = v0;
            }
            if (R + 8 < B) {
                if (ok0 && ok1) *(float2*)&g_S[(size_t)(R + 8) * N + n] = make_float2(v2, v3);
                else if (ok0) g_S[(size_t)(R + 8) * N + n] = v2;
            }
            if (ok0) { mn0 = fminf(mn0, v0); mn1 = fminf(mn1, v2); }
            if (ok1) { mn0 = fminf(mn0, v1); mn1 = fminf(mn1, v3); }
        }
        // reduce over fc (lanes differing in low 2 bits share the row)
        #pragma unroll
        for (int off = 1; off < 4; off <<= 1) {
            mn0 = fminf(mn0, __shfl_xor_sync(0xffffffffu, mn0, off));
            mn1 = fminf(mn1, __shfl_xor_sync(0xffffffffu, mn1, off));
        }
        if (fc == 0) {
            atomicMin(&bmu[R], enc(mn0));
            atomicMin(&bmu[R + 8], enc(mn1));
        }
    }
    __syncthreads();
    if (tid < 256 && tid < B)
        g_blkmin[tid * ntiles + blockIdx.x] = dec(bmu[tid]);
}

// ---------------- select: blockmin threshold -> sparse gather -> exact refine ----------------
__global__ __launch_bounds__(256)
void select_kernel(const float* __restrict__ Q, const int* __restrict__ qsys,
                   const float* __restrict__ X, const float* __restrict__ Y,
                   const int* __restrict__ sys, const float* __restrict__ W,
                   const float* __restrict__ bias, float* __restrict__ out,
                   int B, int N, int ntiles)
{
    __shared__ float qs[DEMB];
    __shared__ float red[256];
    __shared__ unsigned long long buf[BUFCAP];   // first 8KB reused as float sort arena
    __shared__ int   blist[256];
    __shared__ int   sh_cnt, sh_nblk;
    __shared__ float cv[K2];
    __shared__ int   ci[K2];
    __shared__ unsigned long long rkey[K2];
    __shared__ float selv[KSEL];
    __shared__ int   seli[KSEL];

    const int b = blockIdx.x, tid = threadIdx.x;
    const int warp = tid >> 5, lane = tid & 31;

    // query row + q2
    float q2p = 0.f;
    for (int k = tid; k < DEMB; k += 256) {
        float v = Q[(size_t)b * DEMB + k];
        qs[k] = v; q2p = fmaf(v, v, q2p);
    }
    red[tid] = q2p; __syncthreads();
    for (int s = 128; s > 0; s >>= 1) { if (tid < s) red[tid] += red[tid + s]; __syncthreads(); }
    const float q2 = red[0];

    // load blockmins into sort arena (pad to BMPAD)
    float* bms = (float*)buf;
    const float* bmrow = &g_blkmin[b * ntiles];
    for (int i = tid; i < BMPAD; i += 256)
        bms[i] = (i < ntiles) ? bmrow[i] : CUDART_INF_F;
    if (tid == 0) { sh_cnt = 0; sh_nblk = 0; }
    __syncthreads();

    // bitonic sort BMPAD floats ascending -> t0 = 64th smallest blockmin
    for (int k = 2; k <= BMPAD; k <<= 1)
        for (int j = k >> 1; j > 0; j >>= 1) {
            for (int i = tid; i < BMPAD; i += 256) {
                int ixj = i ^ j;
                if (ixj > i) {
                    float a = bms[i], c = bms[ixj];
                    if ((a > c) == ((i & k) == 0)) { bms[i] = c; bms[ixj] = a; }
                }
            }
            __syncthreads();
        }
    const float t0 = bms[K2 - 1];
    __syncthreads();

    // enumerate qualifying blocks (re-read from global; arena was destroyed)
    for (int i = tid; i < ntiles; i += 256)
        if (bmrow[i] <= t0) {
            int p = atomicAdd(&sh_nblk, 1);
            if (p < 256) blist[p] = i;
        }
    __syncthreads();
    int nblk = sh_nblk; if (nblk > 256) nblk = 256;

    // re-init buf then gather elements <= t0
    for (int i = tid; i < BUFCAP; i += 256) buf[i] = ~0ULL;
    __syncthreads();
    const float* srow = &g_S[(size_t)b * N];
    for (int e = tid; e < nblk * TILE_N; e += 256) {
        int blk = blist[e >> 7];
        int n = blk * TILE_N + (e & (TILE_N - 1));
        if (n < N) {
            float v = srow[n];
            if (v <= t0) {
                int p = atomicAdd(&sh_cnt, 1);
                if (p < BUFCAP) buf[p] = mkkey(v, n);
            }
        }
    }
    __syncthreads();
    int cnt = sh_cnt; if (cnt > BUFCAP) cnt = BUFCAP;

    // bitonic sort candidate keys
    int P = K2; while (P < cnt) P <<= 1;
    for (int k = 2; k <= P; k <<= 1)
        for (int j = k >> 1; j > 0; j >>= 1) {
            for (int i = tid; i < P; i += 256) {
                int ixj = i ^ j;
                if (ixj > i) {
                    unsigned long long a = buf[i], c = buf[ixj];
                    if ((a > c) == ((i & k) == 0)) { buf[i] = c; buf[ixj] = a; }
                }
            }
            __syncthreads();
        }

    if (tid < K2) ci[tid] = (int)(buf[tid] & 0xffffffffu);
    __syncthreads();

    // exact fp32 refine
    for (int c = warp; c < K2; c += 8) {
        const float* xr = &X[(size_t)ci[c] * DEMB];
        float dot = 0.f, xx = 0.f;
        for (int k = lane; k < DEMB; k += 32) {
            float xv = xr[k];
            dot = fmaf(qs[k], xv, dot);
            xx  = fmaf(xv, xv, xx);
        }
        #pragma unroll
        for (int off = 16; off > 0; off >>= 1) {
            dot += __shfl_xor_sync(0xffffffffu, dot, off);
            xx  += __shfl_xor_sync(0xffffffffu, xx,  off);
        }
        if (lane == 0) cv[c] = fmaf(-2.f, dot, q2 + xx);
    }
    __syncthreads();

    // rank 64 refined -> top-32 by (d2, idx)
    if (tid < K2) rkey[tid] = mkkey(cv[tid], ci[tid]);
    __syncthreads();
    if (tid < K2) {
        unsigned long long me = rkey[tid];
        int rank = 0;
        #pragma unroll
        for (int j = 0; j < K2; j++) rank += (rkey[j] < me);
        if (rank < KSEL) { selv[rank] = cv[tid]; seli[rank] = ci[tid]; }
    }
    __syncthreads();

    // local layer + prefix softmax
    if (tid < KSEL) {
        float d2v = selv[tid];
        int   idx = seli[tid];
        float sc  = Y[idx];
        float nd  = (sys[idx] == qsys[b]) ? fmaf(d2v, W[1], bias[1]) : fmaf(d2v, W[0], bias[0]);
        float neg = -nd;
        float mmax = neg;
        #pragma unroll
        for (int off = 16; off > 0; off >>= 1)
            mmax = fmaxf(mmax, __shfl_xor_sync(0xffffffffu, mmax, off));
        float w  = expf(neg - mmax);
        float ws = w * sc;
        float cw = w, cws = ws;
        #pragma unroll
        for (int off = 1; off < KSEL; off <<= 1) {
            float tw  = __shfl_up_sync(0xffffffffu, cw,  off);
            float tws = __shfl_up_sync(0xffffffffu, cws, off);
            if (tid >= off) { cw += tw; cws += tws; }
        }
        out[(size_t)b * KSEL + tid] = nd;
        out[(size_t)B * KSEL + (size_t)b * KSEL + tid] = cws / cw;
    }
}

extern "C" void kernel_launch(void* const* d_in, const int* in_sizes, int n_in,
                              void* d_out, int out_size)
{
    const float* Q    = (const float*)d_in[0];
    const int*   qsys = (const int*)  d_in[1];
    const float* X    = (const float*)d_in[2];
    const float* Y    = (const float*)d_in[3];
    const int*   sys  = (const int*)  d_in[4];
    const float* W    = (const float*)d_in[5];
    const float* bias = (const float*)d_in[6];
    float* out = (float*)d_out;

    int B = in_sizes[1];
    int N = in_sizes[3];
    int ntiles = (N + TILE_N - 1) / TILE_N;

    const int smem = STAGES * STAGE_BYTES;   // 90112
    cudaFuncSetAttribute(gemm_hmma_kernel, cudaFuncAttributeMaxDynamicSharedMemorySize, smem);

    convq_kernel<<<(MAXB * DEMB + 255) / 256, 256>>>(Q, B * DEMB);
    gemm_hmma_kernel<<<ntiles, 512, smem>>>(X, B, N, ntiles);
    select_kernel<<<B, 256>>>(Q, qsys, X, Y, sys, W, bias, out, B, N, ntiles);
}

// round 6
// speedup vs baseline: 33.6881x; 1.1657x over previous
#include <cuda_runtime.h>
#include <cuda_bf16.h>
#include <math_constants.h>
#include <cstdint>
#include <cstddef>

#define DEMB 768
#define KSEL 32
#define K2   128
#define TILE_N 128
#define KC   32                 // k elements per chunk
#define NCH  (DEMB / KC)        // 24
#define STAGES 4
#define MAXB 256
#define MAXN 200000
#define MAXT ((MAXN + TILE_N - 1) / TILE_N)   // 1563
#define BUFCAP 4096
#define BMPAD 2048

// stage layout: A fp8 (256 rows x 48B pitch, 32B data) then B fp32 (128 rows x 128B, swizzled)
#define A_PITCH 48
#define A_BYTES (256 * A_PITCH)            // 12288
#define B_BYTES (128 * 128)                // 16384
#define STAGE_BYTES (A_BYTES + B_BYTES)    // 28672

// ---- device scratch ----
__device__ __align__(16) uint8_t g_Q8[MAXB * DEMB];
__device__ __align__(16) float g_S[(size_t)MAXB * (size_t)MAXN];
__device__ __align__(16) float g_blkmin[MAXB * MAXT];

__device__ __forceinline__ uint32_t smem_u32(const void* p) {
    uint32_t a;
    asm("{ .reg .u64 t; cvta.to.shared.u64 t, %1; cvt.u32.u64 %0, t; }" : "=r"(a) : "l"(p));
    return a;
}
__device__ __forceinline__ void cp16(uint32_t dst, const void* src) {
    asm volatile("cp.async.ca.shared.global [%0], [%1], 16;" :: "r"(dst), "l"(src));
}
#define CP_COMMIT() asm volatile("cp.async.commit_group;" ::: "memory")
#define CP_WAIT2()  asm volatile("cp.async.wait_group 2;" ::: "memory")

__device__ __forceinline__ uint32_t pack_e4m3(float f0, float f1, float f2, float f3) {
    uint16_t lo, hi;
    asm("cvt.rn.satfinite.e4m3x2.f32 %0, %1, %2;" : "=h"(lo) : "f"(f1), "f"(f0));
    asm("cvt.rn.satfinite.e4m3x2.f32 %0, %1, %2;" : "=h"(hi) : "f"(f3), "f"(f2));
    return (uint32_t)lo | ((uint32_t)hi << 16);
}
__device__ __forceinline__ void mma_fp8(float* c, const uint32_t* a, const uint32_t* b) {
    asm volatile(
        "mma.sync.aligned.m16n8k32.row.col.f32.e4m3.e4m3.f32 "
        "{%0,%1,%2,%3}, {%4,%5,%6,%7}, {%8,%9}, {%0,%1,%2,%3};"
        : "+f"(c[0]), "+f"(c[1]), "+f"(c[2]), "+f"(c[3])
        : "r"(a[0]), "r"(a[1]), "r"(a[2]), "r"(a[3]), "r"(b[0]), "r"(b[1]));
}
__device__ __forceinline__ unsigned enc(float f) {
    unsigned u = __float_as_uint(f);
    return (u & 0x80000000u) ? ~u : (u | 0x80000000u);
}
__device__ __forceinline__ float dec(unsigned u) {
    u = (u & 0x80000000u) ? (u & 0x7fffffffu) : ~u;
    return __uint_as_float(u);
}
__device__ __forceinline__ unsigned long long mkkey(float v, int idx) {
    return ((unsigned long long)enc(v) << 32) | (unsigned)idx;
}

// ---------------- Q fp32 -> e4m3 (zero-pad to MAXB rows) ----------------
__global__ void convq_kernel(const float* __restrict__ Q, int total) {
    int i = blockIdx.x * blockDim.x + threadIdx.x;
    if (i < MAXB * DEMB / 4) {
        int e = i * 4;
        float4 v = make_float4(0.f, 0.f, 0.f, 0.f);
        if (e < total) v = *(const float4*)&Q[e];
        ((uint32_t*)g_Q8)[i] = pack_e4m3(v.x, v.y, v.z, v.w);
    }
}

// ---------------- FP8 MMA GEMM, M=256 x N-tile=128, cp.async 4-stage ----------------
__global__ __launch_bounds__(512, 1)
void gemm_fp8_kernel(const float* __restrict__ X, int B, int N, int ntiles)
{
    extern __shared__ __align__(16) char dsm[];
    __shared__ float    x2p[TILE_N];
    __shared__ unsigned bmu[256];

    const int tid  = threadIdx.x;
    const int lane = tid & 31;
    const int warp = tid >> 5;
    const int wm = warp >> 2, wn = warp & 3;
    const int fr = lane >> 2, fc = lane & 3;
    const int n0 = blockIdx.x * TILE_N;

    const uint32_t sb = smem_u32(dsm);

    // A cp.async: one 16B chunk per thread (256 rows x 2 chunks)
    const int rA = tid >> 1, hA = tid & 1;
    const char* asrc = (const char*)g_Q8 + (size_t)rA * DEMB + hA * 16;
    const uint32_t adst = sb + rA * A_PITCH + hA * 16;

    // B cp.async: two 16B chunks per thread (128 rows x 8 chunks, XOR-swizzled)
    const int rB0 = tid >> 3,        cB0 = tid & 7;
    const int rB1 = (tid + 512) >> 3, cB1 = tid & 7;   // rB1 = rB0 + 64
    const float* bsrc0 = &X[(size_t)min(n0 + rB0, N - 1) * DEMB + cB0 * 4];
    const float* bsrc1 = &X[(size_t)min(n0 + rB1, N - 1) * DEMB + cB1 * 4];
    const uint32_t bdst0 = sb + A_BYTES + rB0 * 128 + ((cB0 ^ ((rB0 & 1) << 2)) * 16);
    const uint32_t bdst1 = sb + A_BYTES + rB1 * 128 + ((cB1 ^ ((rB1 & 1) << 2)) * 16);

    if (tid < 256) bmu[tid] = 0xFFFFFFFFu;

    // prologue: stages 0..2
    #pragma unroll
    for (int s = 0; s < 3; s++) {
        cp16(adst + s * STAGE_BYTES, asrc + s * KC);
        cp16(bdst0 + s * STAGE_BYTES, bsrc0 + s * KC);
        cp16(bdst1 + s * STAGE_BYTES, bsrc1 + s * KC);
        CP_COMMIT();
    }

    float acc[4][4][4];
    #pragma unroll
    for (int mi = 0; mi < 4; mi++)
        #pragma unroll
        for (int ni = 0; ni < 4; ni++)
            #pragma unroll
            for (int r = 0; r < 4; r++) acc[mi][ni][r] = 0.f;

    float x2a = 0.f, x2b = 0.f;   // partial x2 for rows (tid>>3) and (tid>>3)+64

    for (int ch = 0; ch < NCH; ch++) {
        const int st = ch & 3;
        CP_WAIT2();
        __syncthreads();

        if (ch + 3 < NCH) {
            const int so = ((ch + 3) & 3) * STAGE_BYTES;
            const int ko = (ch + 3) * KC;
            cp16(adst + so, asrc + ko);
            cp16(bdst0 + so, bsrc0 + ko);
            cp16(bdst1 + so, bsrc1 + ko);
        }
        CP_COMMIT();

        const uint32_t Abu = sb + st * STAGE_BYTES;
        const char* Ab = dsm + st * STAGE_BYTES;
        const char* Bb = Ab + A_BYTES;

        // x2 accumulation: physically-linear reads (conflict-free)
        {
            float4 v0 = *(const float4*)(Bb + tid * 16);
            float4 v1 = *(const float4*)(Bb + (tid + 512) * 16);
            x2a += fmaf(v0.x, v0.x, fmaf(v0.y, v0.y, fmaf(v0.z, v0.z, v0.w * v0.w)));
            x2b += fmaf(v1.x, v1.x, fmaf(v1.y, v1.y, fmaf(v1.z, v1.z, v1.w * v1.w)));
        }

        // B fragments: fp32 (swizzled LDS.128) -> e4m3
        uint32_t bf[4][2];
        const int psw = (fr & 1) << 2;
        #pragma unroll
        for (int ni = 0; ni < 4; ni++) {
            const int n = wn * 32 + ni * 8 + fr;
            float4 f0 = *(const float4*)(Bb + n * 128 + ((fc ^ psw) * 16));
            float4 f1 = *(const float4*)(Bb + n * 128 + (((4 + fc) ^ psw) * 16));
            bf[ni][0] = pack_e4m3(f0.x, f0.y, f0.z, f0.w);
            bf[ni][1] = pack_e4m3(f1.x, f1.y, f1.z, f1.w);
        }

        // A fragments + MMAs
        #pragma unroll
        for (int mi = 0; mi < 4; mi++) {
            const int row = wm * 64 + mi * 16 + fr;
            uint32_t a[4];
            a[0] = *(const uint32_t*)(Ab + row * A_PITCH + fc * 4);
            a[1] = *(const uint32_t*)(Ab + (row + 8) * A_PITCH + fc * 4);
            a[2] = *(const uint32_t*)(Ab + row * A_PITCH + 16 + fc * 4);
            a[3] = *(const uint32_t*)(Ab + (row + 8) * A_PITCH + 16 + fc * 4);
            #pragma unroll
            for (int ni = 0; ni < 4; ni++)
                mma_fp8(acc[mi][ni], a, bf[ni]);
        }
        (void)Abu;
        __syncthreads();
    }

    // reduce x2 partials: rows tid>>3 and (tid>>3)+64, 8 threads each
    x2a += __shfl_down_sync(0xffffffffu, x2a, 4, 8);
    x2a += __shfl_down_sync(0xffffffffu, x2a, 2, 8);
    x2a += __shfl_down_sync(0xffffffffu, x2a, 1, 8);
    x2b += __shfl_down_sync(0xffffffffu, x2b, 4, 8);
    x2b += __shfl_down_sync(0xffffffffu, x2b, 2, 8);
    x2b += __shfl_down_sync(0xffffffffu, x2b, 1, 8);
    if ((tid & 7) == 0) {
        x2p[tid >> 3] = x2a;
        x2p[(tid >> 3) + 64] = x2b;
    }
    __syncthreads();

    // ---- epilogue: dist = x2 - 2*dot, store + blockmin ----
    #pragma unroll
    for (int mi = 0; mi < 4; mi++) {
        const int R = wm * 64 + mi * 16 + fr;
        float mn0 = CUDART_INF_F, mn1 = CUDART_INF_F;
        #pragma unroll
        for (int ni = 0; ni < 4; ni++) {
            const int c = wn * 32 + ni * 8 + 2 * fc;
            const int n = n0 + c;
            const bool ok0 = n < N, ok1 = (n + 1) < N;
            float x2c = x2p[c], x2d = x2p[c + 1];
            float v0 = fmaf(-2.f, acc[mi][ni][0], x2c);
            float v1 = fmaf(-2.f, acc[mi][ni][1], x2d);
            float v2 = fmaf(-2.f, acc[mi][ni][2], x2c);
            float v3 = fmaf(-2.f, acc[mi][ni][3], x2d);
            if (R < B) {
                if (ok0 && ok1) *(float2*)&g_S[(size_t)R * N + n] = make_float2(v0, v1);
                else if (ok0) g_S[(size_t)R * N + n] = v0;
            }
            if (R + 8 < B) {
                if (ok0 && ok1) *(float2*)&g_S[(size_t)(R + 8) * N + n] = make_float2(v2, v3);
                else if (ok0) g_S[(size_t)(R + 8) * N + n] = v2;
            }
            if (ok0) { mn0 = fminf(mn0, v0); mn1 = fminf(mn1, v2); }
            if (ok1) { mn0 = fminf(mn0, v1); mn1 = fminf(mn1, v3); }
        }
        #pragma unroll
        for (int off = 1; off < 4; off <<= 1) {
            mn0 = fminf(mn0, __shfl_xor_sync(0xffffffffu, mn0, off));
            mn1 = fminf(mn1, __shfl_xor_sync(0xffffffffu, mn1, off));
        }
        if (fc == 0) {
            atomicMin(&bmu[R], enc(mn0));
            atomicMin(&bmu[R + 8], enc(mn1));
        }
    }
    __syncthreads();
    if (tid < 256 && tid < B)
        g_blkmin[tid * ntiles + blockIdx.x] = dec(bmu[tid]);
}

// ---------------- select: blockmin threshold -> sparse gather -> exact refine ----------------
__global__ __launch_bounds__(256)
void select_kernel(const float* __restrict__ Q, const int* __restrict__ qsys,
                   const float* __restrict__ X, const float* __restrict__ Y,
                   const int* __restrict__ sys, const float* __restrict__ W,
                   const float* __restrict__ bias, float* __restrict__ out,
                   int B, int N, int ntiles)
{
    __shared__ float qs[DEMB];
    __shared__ float red[256];
    __shared__ unsigned long long buf[BUFCAP];   // first 8KB reused as float sort arena
    __shared__ int   blist[1024];
    __shared__ int   sh_cnt, sh_nblk;
    __shared__ float cv[K2];
    __shared__ int   ci[K2];
    __shared__ unsigned long long rkey[K2];
    __shared__ float selv[KSEL];
    __shared__ int   seli[KSEL];

    const int b = blockIdx.x, tid = threadIdx.x;
    const int warp = tid >> 5, lane = tid & 31;

    // query row + q2
    float q2p = 0.f;
    for (int k = tid; k < DEMB; k += 256) {
        float v = Q[(size_t)b * DEMB + k];
        qs[k] = v; q2p = fmaf(v, v, q2p);
    }
    red[tid] = q2p; __syncthreads();
    for (int s = 128; s > 0; s >>= 1) { if (tid < s) red[tid] += red[tid + s]; __syncthreads(); }
    const float q2 = red[0];

    // load blockmins into sort arena (pad to BMPAD)
    float* bms = (float*)buf;
    const float* bmrow = &g_blkmin[b * ntiles];
    for (int i = tid; i < BMPAD; i += 256)
        bms[i] = (i < ntiles) ? bmrow[i] : CUDART_INF_F;
    if (tid == 0) { sh_cnt = 0; sh_nblk = 0; }
    __syncthreads();

    // bitonic sort BMPAD floats ascending -> t0 = K2-th smallest blockmin
    for (int k = 2; k <= BMPAD; k <<= 1)
        for (int j = k >> 1; j > 0; j >>= 1) {
            for (int i = tid; i < BMPAD; i += 256) {
                int ixj = i ^ j;
                if (ixj > i) {
                    float a = bms[i], c = bms[ixj];
                    if ((a > c) == ((i & k) == 0)) { bms[i] = c; bms[ixj] = a; }
                }
            }
            __syncthreads();
        }
    const float t0 = bms[K2 - 1];
    __syncthreads();

    // enumerate qualifying blocks
    for (int i = tid; i < ntiles; i += 256)
        if (bmrow[i] <= t0) {
            int p = atomicAdd(&sh_nblk, 1);
            if (p < 1024) blist[p] = i;
        }
    __syncthreads();
    int nblk = sh_nblk; if (nblk > 1024) nblk = 1024;

    // re-init buf then gather elements <= t0
    for (int i = tid; i < BUFCAP; i += 256) buf[i] = ~0ULL;
    __syncthreads();
    const float* srow = &g_S[(size_t)b * N];
    for (int e = tid; e < nblk * TILE_N; e += 256) {
        int blk = blist[e >> 7];
        int n = blk * TILE_N + (e & (TILE_N - 1));
        if (n < N) {
            float v = srow[n];
            if (v <= t0) {
                int p = atomicAdd(&sh_cnt, 1);
                if (p < BUFCAP) buf[p] = mkkey(v, n);
            }
        }
    }
    __syncthreads();
    int cnt = sh_cnt; if (cnt > BUFCAP) cnt = BUFCAP;

    // bitonic sort candidate keys
    int P = K2; while (P < cnt) P <<= 1;
    for (int k = 2; k <= P; k <<= 1)
        for (int j = k >> 1; j > 0; j >>= 1) {
            for (int i = tid; i < P; i += 256) {
                int ixj = i ^ j;
                if (ixj > i) {
                    unsigned long long a = buf[i], c = buf[ixj];
                    if ((a > c) == ((i & k) == 0)) { buf[i] = c; buf[ixj] = a; }
                }
            }
            __syncthreads();
        }

    if (tid < K2) ci[tid] = (int)(buf[tid] & 0xffffffffu);
    __syncthreads();

    // exact fp32 refine of K2 candidates
    for (int c = warp; c < K2; c += 8) {
        const float* xr = &X[(size_t)ci[c] * DEMB];
        float dot = 0.f, xx = 0.f;
        for (int k = lane; k < DEMB; k += 32) {
            float xv = xr[k];
            dot = fmaf(qs[k], xv, dot);
            xx  = fmaf(xv, xv, xx);
        }
        #pragma unroll
        for (int off = 16; off > 0; off >>= 1) {
            dot += __shfl_xor_sync(0xffffffffu, dot, off);
            xx  += __shfl_xor_sync(0xffffffffu, xx,  off);
        }
        if (lane == 0) cv[c] = fmaf(-2.f, dot, q2 + xx);
    }
    __syncthreads();

    // rank K2 refined -> top-32 by (d2, idx)
    if (tid < K2) rkey[tid] = mkkey(cv[tid], ci[tid]);
    __syncthreads();
    if (tid < K2) {
        unsigned long long me = rkey[tid];
        int rank = 0;
        #pragma unroll
        for (int j = 0; j < K2; j++) rank += (rkey[j] < me);
        if (rank < KSEL) { selv[rank] = cv[tid]; seli[rank] = ci[tid]; }
    }
    __syncthreads();

    // local layer + prefix softmax
    if (tid < KSEL) {
        float d2v = selv[tid];
        int   idx = seli[tid];
        float sc  = Y[idx];
        float nd  = (sys[idx] == qsys[b]) ? fmaf(d2v, W[1], bias[1]) : fmaf(d2v, W[0], bias[0]);
        float neg = -nd;
        float mmax = neg;
        #pragma unroll
        for (int off = 16; off > 0; off >>= 1)
            mmax = fmaxf(mmax, __shfl_xor_sync(0xffffffffu, mmax, off));
        float w  = expf(neg - mmax);
        float ws = w * sc;
        float cw = w, cws = ws;
        #pragma unroll
        for (int off = 1; off < KSEL; off <<= 1) {
            float tw  = __shfl_up_sync(0xffffffffu, cw,  off);
            float tws = __shfl_up_sync(0xffffffffu, cws, off);
            if (tid >= off) { cw += tw; cws += tws; }
        }
        out[(size_t)b * KSEL + tid] = nd;
        out[(size_t)B * KSEL + (size_t)b * KSEL + tid] = cws / cw;
    }
}

extern "C" void kernel_launch(void* const* d_in, const int* in_sizes, int n_in,
                              void* d_out, int out_size)
{
    const float* Q    = (const float*)d_in[0];
    const int*   qsys = (const int*)  d_in[1];
    const float* X    = (const float*)d_in[2];
    const float* Y    = (const float*)d_in[3];
    const int*   sys  = (const int*)  d_in[4];
    const float* W    = (const float*)d_in[5];
    const float* bias = (const float*)d_in[6];
    float* out = (float*)d_out;

    int B = in_sizes[1];
    int N = in_sizes[3];
    int ntiles = (N + TILE_N - 1) / TILE_N;

    const int smem = STAGES * STAGE_BYTES;   // 114688
    cudaFuncSetAttribute(gemm_fp8_kernel, cudaFuncAttributeMaxDynamicSharedMemorySize, smem);

    convq_kernel<<<(MAXB * DEMB / 4 + 255) / 256, 256>>>(Q, B * DEMB);
    gemm_fp8_kernel<<<ntiles, 512, smem>>>(X, B, N, ntiles);
    select_kernel<<<B, 256>>>(Q, qsys, X, Y, sys, W, bias, out, B, N, ntiles);
}